// round 11
// baseline (speedup 1.0000x reference)
#include <cuda_runtime.h>
#include <cuda_bf16.h>
#include <cstdint>

#define LSEQ 4096
#define DIN  512
#define NH   8
#define NB   2
#define NCTA 128

typedef unsigned short ushort_t;
static const size_t bS = 512 * 512;
static const size_t bX = (size_t)LSEQ * DIN;

// ---------------- device scratch ----------------
__device__ __align__(256) ushort_t g_xh [NB * LSEQ * DIN];
__device__ __align__(256) ushort_t g_xl [NB * LSEQ * DIN];
__device__ __align__(256) ushort_t g_xTh[NB * DIN * LSEQ];
__device__ __align__(256) ushort_t g_xTl[NB * DIN * LSEQ];
__device__ __align__(256) float    g_Gp [NB * 4 * 512 * 512];
__device__ __align__(256) ushort_t g_Gh [NB * 512 * 512];
__device__ __align__(256) ushort_t g_Gl [NB * 512 * 512];
__device__ __align__(256) ushort_t g_PTh[NB * 512 * 512];
__device__ __align__(256) ushort_t g_PTl[NB * 512 * 512];
__device__ __align__(256) ushort_t g_RTh[NB * NH * 64 * 64];
__device__ __align__(256) ushort_t g_RTl[NB * NH * 64 * 64];
__device__ __align__(256) ushort_t g_Uh [NB * 512 * 512];
__device__ __align__(256) ushort_t g_Ul [NB * 512 * 512];
__device__ __align__(256) ushort_t g_CTh[NB * 512 * 512];
__device__ __align__(256) ushort_t g_CTl[NB * 512 * 512];
__device__ __align__(256) ushort_t g_Wkbh[512 * 512];     // [c=h*64+k][m]
__device__ __align__(256) ushort_t g_Wkbl[512 * 512];
__device__ __align__(256) ushort_t g_Wobh[512 * 512];     // [o][hv]
__device__ __align__(256) ushort_t g_Wobl[512 * 512];
__device__ __align__(256) ushort_t g_WvTh[512 * 512];     // [hv][n]
__device__ __align__(256) ushort_t g_WvTl[512 * 512];
__device__ __align__(256) ushort_t g_Wqbh[NH * 512 * 64]; // [h*512+j][k]
__device__ __align__(256) ushort_t g_Wqbl[NH * 512 * 64];

__device__ unsigned g_cnt = 0;
__device__ unsigned g_rel = 0;

// ---------------- helpers ----------------
#define SWZ(o) ((o) ^ (((o) >> 3) & 0x70))

__device__ __forceinline__ uint32_t smem_u32(const void* p) {
    uint32_t a;
    asm("{ .reg .u64 t; cvta.to.shared.u64 t, %1; cvt.u32.u64 %0, t; }" : "=r"(a) : "l"(p));
    return a;
}
__device__ __forceinline__ ushort_t f2bf(float v) {
    __nv_bfloat16 b = __float2bfloat16(v);
    return *reinterpret_cast<ushort_t*>(&b);
}
__device__ __forceinline__ float bfhi(ushort_t h) {
    return __uint_as_float(((uint32_t)h) << 16);
}
__device__ __forceinline__ void ldsm4(uint32_t* f, uint32_t addr) {
    asm volatile("ldmatrix.sync.aligned.m8n8.x4.shared.b16 {%0,%1,%2,%3}, [%4];"
                 : "=r"(f[0]), "=r"(f[1]), "=r"(f[2]), "=r"(f[3]) : "r"(addr));
}
__device__ __forceinline__ void mma16816(float* d, const uint32_t* a, const uint32_t* b) {
    asm volatile("mma.sync.aligned.m16n8k16.row.col.f32.bf16.bf16.f32 "
                 "{%0,%1,%2,%3}, {%4,%5,%6,%7}, {%8,%9}, {%0,%1,%2,%3};"
                 : "+f"(d[0]), "+f"(d[1]), "+f"(d[2]), "+f"(d[3])
                 : "r"(a[0]), "r"(a[1]), "r"(a[2]), "r"(a[3]), "r"(b[0]), "r"(b[1]));
}
__device__ __forceinline__ void cpa16(uint32_t s, const void* g) {
    asm volatile("cp.async.cg.shared.global [%0], [%1], 16;" :: "r"(s), "l"(g) : "memory");
}
#define CP_COMMIT() asm volatile("cp.async.commit_group;" ::: "memory")
#define CP_WAIT(n)  asm volatile("cp.async.wait_group %0;" :: "n"(n) : "memory")

// Grid barrier: cumulative epoch, replay-safe (relbase snapshot at entry).
__device__ __forceinline__ void gbar(unsigned relbase, unsigned ph) {
    __syncthreads();
    if (threadIdx.x == 0) {
        __threadfence();
        unsigned a = atomicAdd(&g_cnt, 1u);
        if (a == NCTA - 1) {
            atomicExch(&g_cnt, 0u);
            __threadfence();
            atomicAdd(&g_rel, 1u);
        } else {
            while (atomicAdd(&g_rel, 0u) < relbase + ph) { __nanosleep(64); }
        }
        __threadfence();
    }
    __syncthreads();
}

// ===========================================================================
// Generic bf16x3 GEMM via mma.sync (HMMA): used for the two BIG GEMMs only
// (BM=BN=128, fp32 out). 4-stage cp.async pipeline.
// ===========================================================================
template <int BM, int BN, int EPI>
__global__ void __launch_bounds__(256, 1)
gemm_bf3(const ushort_t* __restrict__ Ah, const ushort_t* __restrict__ Al,
         const ushort_t* __restrict__ Bh, const ushort_t* __restrict__ Bl,
         float* __restrict__ Cf, ushort_t* __restrict__ Ch, ushort_t* __restrict__ Cl,
         int K, int lda, int ldb, int ldc,
         long bA, long slA, long bB, long slB, long bC, long slC, int nsl) {
    constexpr int WM = BM / 2, WN = BN / 4;
    constexpr int MT = WM / 16, NT = WN / 8, PB = WN / 16;
    constexpr int SS = (BM + BN) * 128;
    constexpr int NSTG = 4;

    extern __shared__ char dsm[];
    uint32_t sb = smem_u32(dsm);
    int tid = threadIdx.x, lane = tid & 31, wid = tid >> 5;
    int wm = wid & 1, wn = wid >> 1;

    int z = blockIdx.z, b = z / nsl, sl = z - b * nsl;
    int m0 = blockIdx.y * BM, n0 = blockIdx.x * BN;
    const ushort_t* pAh = Ah + b * bA + sl * slA + (size_t)m0 * lda;
    const ushort_t* pAl = Al + b * bA + sl * slA + (size_t)m0 * lda;
    const ushort_t* pBh = Bh + b * bB + sl * slB + (size_t)n0 * ldb;
    const ushort_t* pBl = Bl + b * bB + sl * slB + (size_t)n0 * ldb;

    float acc[MT][NT][4];
#pragma unroll
    for (int i = 0; i < MT; i++)
#pragma unroll
        for (int j = 0; j < NT; j++)
#pragma unroll
            for (int q = 0; q < 4; q++) acc[i][j][q] = 0.f;

    const int nkt = K >> 5;

    auto load_stage = [&](int stg, int kt, bool pred) {
        if (pred) {
            uint32_t s0 = sb + stg * SS;
            int ke = kt * 32;
#pragma unroll
            for (int c = tid; c < BM * 4; c += 256) {
                int r = c >> 2, sg = c & 3;
                uint32_t o = SWZ((uint32_t)((r >> 1) * 128 + (r & 1) * 64 + sg * 16));
                cpa16(s0 + o,           pAh + (size_t)r * lda + ke + sg * 8);
                cpa16(s0 + BM * 64 + o, pAl + (size_t)r * lda + ke + sg * 8);
            }
#pragma unroll
            for (int c = tid; c < BN * 4; c += 256) {
                int r = c >> 2, sg = c & 3;
                uint32_t o = SWZ((uint32_t)((r >> 1) * 128 + (r & 1) * 64 + sg * 16));
                cpa16(s0 + BM * 128 + o,           pBh + (size_t)r * ldb + ke + sg * 8);
                cpa16(s0 + BM * 128 + BN * 64 + o, pBl + (size_t)r * ldb + ke + sg * 8);
            }
        }
        CP_COMMIT();
    };

#pragma unroll
    for (int s = 0; s < NSTG - 1; s++) load_stage(s, s, s < nkt);

#pragma unroll 1
    for (int kt = 0; kt < nkt; kt++) {
        CP_WAIT(2);
        __syncthreads();
        load_stage((kt + NSTG - 1) & (NSTG - 1), kt + NSTG - 1, kt + NSTG - 1 < nkt);

        uint32_t stb = sb + (kt & (NSTG - 1)) * SS;
#pragma unroll
        for (int ks = 0; ks < 2; ks++) {
            uint32_t ah[MT][4], al[MT][4], bh[PB][4], bl[PB][4];
            int ar  = wm * WM + (lane & 15);
            int akk = ks * 16 + (lane >> 4) * 8;
#pragma unroll
            for (int mt = 0; mt < MT; mt++) {
                int r = ar + mt * 16;
                uint32_t o = SWZ((uint32_t)((r >> 1) * 128 + (r & 1) * 64 + akk * 2));
                ldsm4(ah[mt], stb + o);
                ldsm4(al[mt], stb + BM * 64 + o);
            }
            int bn  = wn * WN + (lane & 7) + ((lane >> 4) & 1) * 8;
            int bkk = ks * 16 + ((lane >> 3) & 1) * 8;
#pragma unroll
            for (int p = 0; p < PB; p++) {
                int r = bn + p * 16;
                uint32_t o = SWZ((uint32_t)((r >> 1) * 128 + (r & 1) * 64 + bkk * 2));
                ldsm4(bh[p], stb + BM * 128 + o);
                ldsm4(bl[p], stb + BM * 128 + BN * 64 + o);
            }
#pragma unroll
            for (int mt = 0; mt < MT; mt++)
#pragma unroll
                for (int nt = 0; nt < NT; nt++) {
                    const uint32_t* fh = &bh[nt >> 1][(nt & 1) * 2];
                    const uint32_t* fl = &bl[nt >> 1][(nt & 1) * 2];
                    mma16816(acc[mt][nt], ah[mt], fh);
                    mma16816(acc[mt][nt], al[mt], fh);
                    mma16816(acc[mt][nt], ah[mt], fl);
                }
        }
    }

    long offC = b * bC + sl * slC;
    int r0 = m0 + wm * WM + (lane >> 2);
    int c0 = n0 + wn * WN + (lane & 3) * 2;
    float* Co = Cf + offC;
#pragma unroll
    for (int mt = 0; mt < MT; mt++)
#pragma unroll
        for (int nt = 0; nt < NT; nt++) {
            int r = r0 + mt * 16, c = c0 + nt * 8;
            *(float2*)&Co[(size_t)r * ldc + c] =
                make_float2(acc[mt][nt][0], acc[mt][nt][1]);
            *(float2*)&Co[(size_t)(r + 8) * ldc + c] =
                make_float2(acc[mt][nt][2], acc[mt][nt][3]);
        }
}

// ===========================================================================
// 64x64 bf16x3 GEMM tile device function (bf16 hi/lo out), 4-stage pipeline.
// Pointers pre-offset; SS=16384, needs 64KB smem.
// ===========================================================================
__device__ __noinline__ void gemm64(char* dsm, uint32_t sb,
        const ushort_t* pAh, const ushort_t* pAl,
        const ushort_t* pBh, const ushort_t* pBl,
        ushort_t* Hh, ushort_t* Hl, int K, int lda, int ldb, int ldc) {
    constexpr int SS = 16384, NSTG = 4;
    int tid = threadIdx.x, lane = tid & 31, wid = tid >> 5;
    int wm = wid & 1, wn = wid >> 1;

    float acc[2][2][4];
#pragma unroll
    for (int i = 0; i < 2; i++)
#pragma unroll
        for (int j = 0; j < 2; j++)
#pragma unroll
            for (int q = 0; q < 4; q++) acc[i][j][q] = 0.f;

    const int nkt = K >> 5;

    auto load_stage = [&](int stg, int kt, bool pred) {
        if (pred) {
            uint32_t s0 = sb + stg * SS;
            int ke = kt * 32;
            int c = tid;                 // 256 == 64*4 exactly
            int r = c >> 2, sg = c & 3;
            uint32_t o = SWZ((uint32_t)((r >> 1) * 128 + (r & 1) * 64 + sg * 16));
            cpa16(s0 + o,         pAh + (size_t)r * lda + ke + sg * 8);
            cpa16(s0 + 4096 + o,  pAl + (size_t)r * lda + ke + sg * 8);
            cpa16(s0 + 8192 + o,  pBh + (size_t)r * ldb + ke + sg * 8);
            cpa16(s0 + 12288 + o, pBl + (size_t)r * ldb + ke + sg * 8);
        }
        CP_COMMIT();
    };

#pragma unroll
    for (int s = 0; s < NSTG - 1; s++) load_stage(s, s, s < nkt);

#pragma unroll 1
    for (int kt = 0; kt < nkt; kt++) {
        CP_WAIT(2);
        __syncthreads();
        load_stage((kt + NSTG - 1) & (NSTG - 1), kt + NSTG - 1, kt + NSTG - 1 < nkt);

        uint32_t stb = sb + (kt & (NSTG - 1)) * SS;
#pragma unroll
        for (int ks = 0; ks < 2; ks++) {
            uint32_t ah[2][4], al[2][4], bh[1][4], bl[1][4];
            int ar  = wm * 32 + (lane & 15);
            int akk = ks * 16 + (lane >> 4) * 8;
#pragma unroll
            for (int mt = 0; mt < 2; mt++) {
                int r = ar + mt * 16;
                uint32_t o = SWZ((uint32_t)((r >> 1) * 128 + (r & 1) * 64 + akk * 2));
                ldsm4(ah[mt], stb + o);
                ldsm4(al[mt], stb + 4096 + o);
            }
            int bn  = wn * 16 + (lane & 7) + ((lane >> 4) & 1) * 8;
            int bkk = ks * 16 + ((lane >> 3) & 1) * 8;
            {
                uint32_t o = SWZ((uint32_t)((bn >> 1) * 128 + (bn & 1) * 64 + bkk * 2));
                ldsm4(bh[0], stb + 8192 + o);
                ldsm4(bl[0], stb + 12288 + o);
            }
#pragma unroll
            for (int mt = 0; mt < 2; mt++)
#pragma unroll
                for (int nt = 0; nt < 2; nt++) {
                    const uint32_t* fh = &bh[0][nt * 2];
                    const uint32_t* fl = &bl[0][nt * 2];
                    mma16816(acc[mt][nt], ah[mt], fh);
                    mma16816(acc[mt][nt], al[mt], fh);
                    mma16816(acc[mt][nt], ah[mt], fl);
                }
        }
    }

    int r0 = wm * 32 + (lane >> 2);
    int c0 = wn * 16 + (lane & 3) * 2;
#pragma unroll
    for (int mt = 0; mt < 2; mt++)
#pragma unroll
        for (int nt = 0; nt < 2; nt++)
#pragma unroll
            for (int hf = 0; hf < 2; hf++) {
                int r = r0 + mt * 16 + hf * 8, c = c0 + nt * 8;
                float v0 = acc[mt][nt][hf * 2], v1 = acc[mt][nt][hf * 2 + 1];
                ushort_t h0 = f2bf(v0), h1 = f2bf(v1);
                *(ushort2*)&Hh[(size_t)r * ldc + c] = make_ushort2(h0, h1);
                *(ushort2*)&Hl[(size_t)r * ldc + c] =
                    make_ushort2(f2bf(v0 - bfhi(h0)), f2bf(v1 - bfhi(h1)));
            }
    __syncthreads();
}

// ===========================================================================
// Fused middle kernel: reduceG -> PT -> RT -> U -> CT  (128 CTAs, 4 barriers)
// ===========================================================================
__global__ void __launch_bounds__(256, 1)
fused_mid() {
    extern __shared__ char dsm[];
    uint32_t sb = smem_u32(dsm);
    int tid = threadIdx.x, cta = blockIdx.x;
    unsigned relbase = 0;
    if (tid == 0) relbase = atomicAdd(&g_rel, 0u);

    // ---- P0: reduce G partials -> bf16 hi/lo ----
    for (int i = cta * 256 + tid; i < NB * 65536; i += NCTA * 256) {
        int b = i >> 16, e = i & 65535;
        const float4* p = (const float4*)g_Gp;
        float4 v = p[(size_t)(b * 4) * 65536 + e];
#pragma unroll
        for (int q = 1; q < 4; q++) {
            float4 t = p[(size_t)(b * 4 + q) * 65536 + e];
            v.x += t.x; v.y += t.y; v.z += t.z; v.w += t.w;
        }
        ushort_t h0 = f2bf(v.x), h1 = f2bf(v.y), h2 = f2bf(v.z), h3 = f2bf(v.w);
        size_t o = (size_t)b * 65536 + e;
        ((ushort4*)g_Gh)[o] = make_ushort4(h0, h1, h2, h3);
        ((ushort4*)g_Gl)[o] = make_ushort4(f2bf(v.x - bfhi(h0)), f2bf(v.y - bfhi(h1)),
                                           f2bf(v.z - bfhi(h2)), f2bf(v.w - bfhi(h3)));
    }
    gbar(relbase, 1);

    // ---- P1: PT[c][n] = sum_m Wkb[c][m] G[n][m]; 128 tasks of 64x64 ----
    {
        int b = cta >> 6, ti = cta & 63;
        int m0 = (ti >> 3) * 64, n0 = (ti & 7) * 64;
        gemm64(dsm, sb,
               g_Wkbh + (size_t)m0 * 512, g_Wkbl + (size_t)m0 * 512,
               g_Gh + (size_t)b * bS + (size_t)n0 * 512,
               g_Gl + (size_t)b * bS + (size_t)n0 * 512,
               g_PTh + (size_t)b * bS + (size_t)m0 * 512 + n0,
               g_PTl + (size_t)b * bS + (size_t)m0 * 512 + n0,
               512, 512, 512, 512);
    }
    gbar(relbase, 2);

    // ---- P2: RT[v][k] = sum_n WvT[hv][n] PT[hk][n] (FFMA, 128 tasks) ----
    {
        float* As = (float*)dsm;        // [8][512]
        int b = cta >> 6, h = (cta >> 3) & 7, vs = cta & 7;
        int row0 = h * 64 + vs * 8;
        for (int i = tid; i < 8 * 128; i += 256) {
            int r = i >> 7, c4 = (i & 127) * 4;
            ushort4 hv = *(const ushort4*)&g_WvTh[(size_t)(row0 + r) * 512 + c4];
            ushort4 lv = *(const ushort4*)&g_WvTl[(size_t)(row0 + r) * 512 + c4];
            *(float4*)&As[r * 512 + c4] =
                make_float4(bfhi(hv.x) + bfhi(lv.x), bfhi(hv.y) + bfhi(lv.y),
                            bfhi(hv.z) + bfhi(lv.z), bfhi(hv.w) + bfhi(lv.w));
        }
        __syncthreads();
        int k = tid & 63, vp = tid >> 6;
        const ushort4* Bh4 = (const ushort4*)(g_PTh + (size_t)b * bS + (size_t)(h * 64 + k) * 512);
        const ushort4* Bl4 = (const ushort4*)(g_PTl + (size_t)b * bS + (size_t)(h * 64 + k) * 512);
        const float4* A0 = (const float4*)(As + (vp * 2 + 0) * 512);
        const float4* A1 = (const float4*)(As + (vp * 2 + 1) * 512);
        float a0 = 0.f, a1 = 0.f;
#pragma unroll 4
        for (int n4 = 0; n4 < 128; n4++) {
            ushort4 bh4 = Bh4[n4], bl4 = Bl4[n4];
            float4 bv = make_float4(bfhi(bh4.x) + bfhi(bl4.x), bfhi(bh4.y) + bfhi(bl4.y),
                                    bfhi(bh4.z) + bfhi(bl4.z), bfhi(bh4.w) + bfhi(bl4.w));
            float4 x0 = A0[n4], x1 = A1[n4];
            a0 += x0.x*bv.x + x0.y*bv.y + x0.z*bv.z + x0.w*bv.w;
            a1 += x1.x*bv.x + x1.y*bv.y + x1.z*bv.z + x1.w*bv.w;
        }
        size_t base = (size_t)(b * 8 + h) * 4096 + (size_t)vs * 8 * 64;
        ushort_t h0 = f2bf(a0), h1 = f2bf(a1);
        g_RTh[base + (vp * 2 + 0) * 64 + k] = h0;
        g_RTl[base + (vp * 2 + 0) * 64 + k] = f2bf(a0 - bfhi(h0));
        g_RTh[base + (vp * 2 + 1) * 64 + k] = h1;
        g_RTl[base + (vp * 2 + 1) * 64 + k] = f2bf(a1 - bfhi(h1));
        __syncthreads();
    }
    gbar(relbase, 3);

    // ---- P3: U[j][h*64+v] = sum_k Wqb[h*512+j][k] RT[v][k] (FFMA, 128 tasks) ----
    {
        float* As = (float*)dsm;                 // [64][69]
        float* Bs = As + 64 * 69;                // [64][69]
        int b = cta >> 6, h = (cta >> 3) & 7, j0 = cta & 7;
        const ushort_t* Ah = g_Wqbh + ((size_t)h * 512 + j0 * 64) * 64;
        const ushort_t* Al = g_Wqbl + ((size_t)h * 512 + j0 * 64) * 64;
        const ushort_t* Bh = g_RTh + (size_t)(b * 8 + h) * 4096;
        const ushort_t* Bl = g_RTl + (size_t)(b * 8 + h) * 4096;
        for (int i = tid; i < 64 * 16; i += 256) {
            int r = i >> 4, c4 = (i & 15) * 4;
            ushort4 a4 = *(const ushort4*)&Ah[r * 64 + c4];
            ushort4 l4 = *(const ushort4*)&Al[r * 64 + c4];
            As[r * 69 + c4+0] = bfhi(a4.x) + bfhi(l4.x);
            As[r * 69 + c4+1] = bfhi(a4.y) + bfhi(l4.y);
            As[r * 69 + c4+2] = bfhi(a4.z) + bfhi(l4.z);
            As[r * 69 + c4+3] = bfhi(a4.w) + bfhi(l4.w);
            ushort4 b4 = *(const ushort4*)&Bh[r * 64 + c4];
            ushort4 m4 = *(const ushort4*)&Bl[r * 64 + c4];
            Bs[r * 69 + c4+0] = bfhi(b4.x) + bfhi(m4.x);
            Bs[r * 69 + c4+1] = bfhi(b4.y) + bfhi(m4.y);
            Bs[r * 69 + c4+2] = bfhi(b4.z) + bfhi(m4.z);
            Bs[r * 69 + c4+3] = bfhi(b4.w) + bfhi(m4.w);
        }
        __syncthreads();
        int tx = tid & 15, ty = tid >> 4;
        float acc[4][4] = {};
#pragma unroll 8
        for (int k = 0; k < 64; k++) {
            float a[4], bb[4];
#pragma unroll
            for (int i = 0; i < 4; i++) a[i]  = As[(ty * 4 + i) * 69 + k];
#pragma unroll
            for (int j = 0; j < 4; j++) bb[j] = Bs[(tx * 4 + j) * 69 + k];
#pragma unroll
            for (int i = 0; i < 4; i++)
#pragma unroll
                for (int j = 0; j < 4; j++) acc[i][j] += a[i] * bb[j];
        }
        size_t ub = (size_t)b * bS;
#pragma unroll
        for (int i = 0; i < 4; i++) {
            int jg = j0 * 64 + ty * 4 + i;
            ushort_t hb[4], lb[4];
#pragma unroll
            for (int j = 0; j < 4; j++) {
                ushort_t hh = f2bf(acc[i][j]);
                hb[j] = hh; lb[j] = f2bf(acc[i][j] - bfhi(hh));
            }
            size_t o = ub + (size_t)jg * 512 + h * 64 + tx * 4;
            *(ushort4*)&g_Uh[o] = make_ushort4(hb[0], hb[1], hb[2], hb[3]);
            *(ushort4*)&g_Ul[o] = make_ushort4(lb[0], lb[1], lb[2], lb[3]);
        }
        __syncthreads();
    }
    gbar(relbase, 4);

    // ---- P4: CT[o][j] = sum_hv Wob[o][hv] U[j][hv]; 128 tasks of 64x64 ----
    {
        int b = cta >> 6, ti = cta & 63;
        int m0 = (ti >> 3) * 64, n0 = (ti & 7) * 64;
        gemm64(dsm, sb,
               g_Wobh + (size_t)m0 * 512, g_Wobl + (size_t)m0 * 512,
               g_Uh + (size_t)b * bS + (size_t)n0 * 512,
               g_Ul + (size_t)b * bS + (size_t)n0 * 512,
               g_CTh + (size_t)b * bS + (size_t)m0 * 512 + n0,
               g_CTl + (size_t)b * bS + (size_t)m0 * 512 + n0,
               512, 512, 512, 512);
    }
}

// ===========================================================================
// Fused input pack
// ===========================================================================
__global__ void pack_all(const float* __restrict__ x, const float* __restrict__ Wq,
                         const float* __restrict__ Wk, const float* __restrict__ Wv,
                         const float* __restrict__ Wo) {
    __shared__ float s[32][33];
    int blk = blockIdx.x, tid = threadIdx.x;
    if (blk < 4096) {                      // x row-major split
        size_t i = (size_t)blk * 256 + tid;
        float4 v = ((const float4*)x)[i];
        ushort_t h0 = f2bf(v.x), h1 = f2bf(v.y), h2 = f2bf(v.z), h3 = f2bf(v.w);
        ((ushort4*)g_xh)[i] = make_ushort4(h0, h1, h2, h3);
        ((ushort4*)g_xl)[i] = make_ushort4(f2bf(v.x - bfhi(h0)), f2bf(v.y - bfhi(h1)),
                                           f2bf(v.z - bfhi(h2)), f2bf(v.w - bfhi(h3)));
    } else if (blk < 8192) {               // x transpose -> xT[d][l]
        int id = blk - 4096;
        int bx = id & 127, by = (id >> 7) & 15, b = id >> 11;
        int r0 = bx * 32, c0 = by * 32;
        int tx = tid & 31, ty = tid >> 5;
        const float* xb = x + (size_t)b * bX;
#pragma unroll
        for (int q = 0; q < 4; q++)
            s[ty + 8 * q][tx] = xb[(size_t)(r0 + ty + 8 * q) * DIN + c0 + tx];
        __syncthreads();
#pragma unroll
        for (int q = 0; q < 4; q++) {
            int cd = ty + 8 * q;
            float v = s[tx][cd];
            ushort_t h = f2bf(v);
            size_t o = ((size_t)b * DIN + c0 + cd) * LSEQ + r0 + tx;
            g_xTh[o] = h;
            g_xTl[o] = f2bf(v - bfhi(h));
        }
    } else if (blk < 9216) {               // Wkb[c][m] = Wk[h][m][k]
        int i = (blk - 8192) * 256 + tid;
        int c = i >> 9, m = i & 511, h = c >> 6, kd = c & 63;
        float v = Wk[h * 32768 + m * 64 + kd];
        ushort_t hh = f2bf(v);
        g_Wkbh[i] = hh; g_Wkbl[i] = f2bf(v - bfhi(hh));
    } else if (blk < 10240) {              // Wob[o][hv] = Wo[hv][o]
        int i = (blk - 9216) * 256 + tid;
        int o = i >> 9, hv = i & 511;
        float v = Wo[hv * 512 + o];
        ushort_t hh = f2bf(v);
        g_Wobh[i] = hh; g_Wobl[i] = f2bf(v - bfhi(hh));
    } else if (blk < 11264) {              // WvT[hv][n] = Wv[h][n][v]
        int i = (blk - 10240) * 256 + tid;
        int row = i >> 9, n = i & 511, h = row >> 6, vv = row & 63;
        float v = Wv[h * 32768 + n * 64 + vv];
        ushort_t hh = f2bf(v);
        g_WvTh[i] = hh; g_WvTl[i] = f2bf(v - bfhi(hh));
    } else {                               // Wqb straight split
        int i = (blk - 11264) * 256 + tid;
        float v = Wq[i];
        ushort_t hh = f2bf(v);
        g_Wqbh[i] = hh; g_Wqbl[i] = f2bf(v - bfhi(hh));
    }
}

// ===========================================================================
extern "C" void kernel_launch(void* const* d_in, const int* in_sizes, int n_in,
                              void* d_out, int out_size) {
    const float* x  = (const float*)d_in[0];
    const float* Wq = (const float*)d_in[1];
    const float* Wk = (const float*)d_in[2];
    const float* Wv = (const float*)d_in[3];
    const float* Wo = (const float*)d_in[4];
    float* out = (float*)d_out;

    cudaFuncSetAttribute(gemm_bf3<128,128,0>, cudaFuncAttributeMaxDynamicSharedMemorySize, 131072);
    cudaFuncSetAttribute(fused_mid,           cudaFuncAttributeMaxDynamicSharedMemorySize, 65536);

    ushort_t *xh,*xl,*xTh,*xTl,*CTh,*CTl;
    float *Gp;
    cudaGetSymbolAddress((void**)&xh,  g_xh);  cudaGetSymbolAddress((void**)&xl,  g_xl);
    cudaGetSymbolAddress((void**)&xTh, g_xTh); cudaGetSymbolAddress((void**)&xTl, g_xTl);
    cudaGetSymbolAddress((void**)&CTh, g_CTh); cudaGetSymbolAddress((void**)&CTl, g_CTl);
    cudaGetSymbolAddress((void**)&Gp,  g_Gp);

    pack_all<<<12288, 256>>>(x, Wq, Wk, Wv, Wo);

    // G[n][m] = sum_l xT[n][l] xT[m][l]; split-K 4, fp32 partials
    gemm_bf3<128,128,0><<<dim3(4,4,8), 256, 131072>>>(
        xTh, xTl, xTh, xTl, Gp, nullptr, nullptr,
        1024, LSEQ, LSEQ, 512,
        (long)bX, 1024, (long)bX, 1024, (long)(4*bS), (long)bS, 4);

    // fused middle: reduceG -> PT -> RT -> U -> CT
    fused_mid<<<NCTA, 256, 65536>>>();

    // out[l][o] = sum_j x[l][j] CT[o][j]
    gemm_bf3<128,128,0><<<dim3(4,32,2), 256, 131072>>>(
        xh, xl, CTh, CTl, out, nullptr, nullptr,
        512, 512, 512, 512,
        (long)bX, 0, (long)bS, 0, (long)bX, 0, 1);
}